// round 16
// baseline (speedup 1.0000x reference)
#include <cuda_runtime.h>
#include <math.h>
#include <cstdint>
#include <float.h>

#define NBIN      512
#define BINSCALE  64.0f
#define THREADS   512
#define NWARP     16
#define KP        8
#define PRED_CTA  256
#define NB_MAX    128
#define MAXM      16384
#define MAXP      32768
#define SLABPAIRS 640
#define BIGF      3.0e37f

// -------- device scratch (static; no allocations) --------
__device__ float  g_msp[(MAXM / 2 + 1) * 8];   // norm-sorted model, pair-interleaved
__device__ float4 g_pu[MAXP];                  // transformed preds (px,py,pz,a)
__device__ float  g_puw[MAXP];
__device__ float4 g_ps[MAXP];                  // norm-sorted preds
__device__ float  g_psw[MAXP];
__device__ int g_mhist[NBIN], g_phist[NBIN], g_mcur[NBIN], g_pcur[NBIN];
__device__ float g_partials[NB_MAX];
__device__ unsigned int g_bar1, g_bar2, g_ticket;

__device__ __forceinline__ int norm_bin(float r) {
    int b = (int)(r * BINSCALE);
    if (b < 0) b = 0;
    if (b > NBIN - 1) b = NBIN - 1;
    return b;
}

__device__ __forceinline__ void grid_bar(unsigned int* ctr, unsigned int tgt) {
    __syncthreads();
    if (threadIdx.x == 0) {
        __threadfence();
        atomicAdd(ctr, 1u);
        while (*((volatile unsigned int*)ctr) < tgt) { }
        __threadfence();
    }
    __syncthreads();
}

// packed f32x2 distance + min for one pair record against KP preds
#define PAIRM(X2, Y2, Z2, W2)                                                  \
    {                                                                          \
        _Pragma("unroll")                                                      \
        for (int k = 0; k < KP; k++) {                                         \
            uint64_t d2;                                                       \
            asm("fma.rn.f32x2 %0, %1, %2, %3;" : "=l"(d2)                      \
                : "l"(qz2[k]), "l"(Z2), "l"(W2));                              \
            asm("fma.rn.f32x2 %0, %1, %2, %0;" : "+l"(d2)                      \
                : "l"(qy2[k]), "l"(Y2));                                       \
            asm("fma.rn.f32x2 %0, %1, %2, %0;" : "+l"(d2)                      \
                : "l"(qx2[k]), "l"(X2));                                       \
            float dlo, dhi;                                                    \
            asm("mov.b64 {%0,%1}, %2;" : "=f"(dlo), "=f"(dhi) : "l"(d2));      \
            m_lo[k] = fminf(m_lo[k], dlo);                                     \
            m_hi[k] = fminf(m_hi[k], dhi);                                     \
        }                                                                      \
    }

#define LDG_PAIR(X2, Y2, Z2, W2, GP)                                           \
    asm("ld.global.nc.v2.u64 {%0,%1}, [%2];"                                   \
        : "=l"(X2), "=l"(Y2) : "l"(GP));                                       \
    asm("ld.global.nc.v2.u64 {%0,%1}, [%2+16];"                                \
        : "=l"(Z2), "=l"(W2) : "l"(GP));

__global__ __launch_bounds__(THREADS, 1)
void cd_kernel(const float* __restrict__ vis,
               const float* __restrict__ tac,
               const float* __restrict__ model,
               const float* __restrict__ scale,
               const float* __restrict__ state,
               float* __restrict__ out,
               int nv, int nt, int nm,
               float wv, float wt, int nbp) {
    __shared__ float s_par[13];
    __shared__ float s_min[NWARP * PRED_CTA];
    __shared__ float s_m1[PRED_CTA];
    __shared__ int s_mstart[NBIN + 1];
    __shared__ int s_pstart[NBIN + 1];
    __shared__ int s_wsum[NWARP];
    __shared__ int s_wlo_i, s_whi_i, s_slab0, s_sp, s_n1, s_n2, s_last;

    const int tid  = threadIdx.x;
    const int lane = tid & 31;
    const int warp = tid >> 5;
    const int ntot0 = nv + nt;
    const int ntot = ntot0 < MAXP ? ntot0 : MAXP;
    const int nmm  = nm < MAXM ? nm : MAXM;
    const int npair = (nmm + 1) >> 1;
    const unsigned int GRID = gridDim.x;
    const int gstride = (int)GRID * THREADS;
    const int gtid = blockIdx.x * THREADS + tid;

    // ---- transform params ----
    if (tid == 0) {
        float oxs = state[3], oys = state[4], ozs = state[5];
        float sx = sinf(oxs), cx = cosf(oxs);
        float sy = sinf(oys), cy = cosf(oys);
        float sz = sinf(ozs), cz = cosf(ozs);
        s_par[0] = cz * cy;
        s_par[1] = cz * sy * sx - sz * cx;
        s_par[2] = cz * sy * cx + sz * sx;
        s_par[3] = sz * cy;
        s_par[4] = sz * sy * sx + cz * cx;
        s_par[5] = sz * sy * cx - cz * sx;
        s_par[6] = -sy;
        s_par[7] = cy * sx;
        s_par[8] = cy * cx;
        s_par[9]  = state[0];
        s_par[10] = state[1];
        s_par[11] = state[2];
        s_par[12] = 1.0f / scale[0];
    }
    __syncthreads();

    // ============ Phase A: histograms + pred transform ============
    for (int j = gtid; j < nmm; j += gstride) {
        float gx = model[3 * j], gy = model[3 * j + 1], gz = model[3 * j + 2];
        float b = fmaf(gx, gx, fmaf(gy, gy, gz * gz));
        atomicAdd(&g_mhist[norm_bin(sqrtf(b))], 1);
    }
    for (int i = gtid; i < ntot; i += gstride) {
        const float* src; int idx; float w;
        if (i < nv) { src = vis; idx = i;      w = wv; }
        else        { src = tac; idx = i - nv; w = wt; }
        float vx = src[3 * idx + 0] - s_par[9];
        float vy = src[3 * idx + 1] - s_par[10];
        float vz = src[3 * idx + 2] - s_par[11];
        float inv_s = s_par[12];
        float px = (vx * s_par[0] + vy * s_par[3] + vz * s_par[6]) * inv_s;
        float py = (vx * s_par[1] + vy * s_par[4] + vz * s_par[7]) * inv_s;
        float pz = (vx * s_par[2] + vy * s_par[5] + vz * s_par[8]) * inv_s;
        float a = fmaf(px, px, fmaf(py, py, pz * pz));
        g_pu[i]  = make_float4(px, py, pz, a);
        g_puw[i] = w;
        atomicAdd(&g_phist[norm_bin(sqrtf(a))], 1);
    }
    grid_bar(&g_bar1, GRID);

    // ============ Phase B: warp-shfl prefix scans (every CTA) ============
    {
        int v = g_mhist[tid];
        int incl = v;
        #pragma unroll
        for (int o = 1; o < 32; o <<= 1) {
            int t = __shfl_up_sync(0xffffffffu, incl, o);
            if (lane >= o) incl += t;
        }
        if (lane == 31) s_wsum[warp] = incl;
        __syncthreads();
        if (warp == 0) {
            int wvv = (lane < NWARP) ? s_wsum[lane] : 0;
            int wi = wvv;
            #pragma unroll
            for (int o = 1; o < 16; o <<= 1) {
                int t = __shfl_up_sync(0xffffffffu, wi, o);
                if (lane >= o) wi += t;
            }
            if (lane < NWARP) s_wsum[lane] = wi - wvv;
        }
        __syncthreads();
        s_mstart[tid] = incl - v + s_wsum[warp];
        if (tid == THREADS - 1) s_mstart[NBIN] = incl + s_wsum[warp];
        __syncthreads();

        int v2 = g_phist[tid];
        int incl2 = v2;
        #pragma unroll
        for (int o = 1; o < 32; o <<= 1) {
            int t = __shfl_up_sync(0xffffffffu, incl2, o);
            if (lane >= o) incl2 += t;
        }
        if (lane == 31) s_wsum[warp] = incl2;
        __syncthreads();
        if (warp == 0) {
            int wvv = (lane < NWARP) ? s_wsum[lane] : 0;
            int wi = wvv;
            #pragma unroll
            for (int o = 1; o < 16; o <<= 1) {
                int t = __shfl_up_sync(0xffffffffu, wi, o);
                if (lane >= o) wi += t;
            }
            if (lane < NWARP) s_wsum[lane] = wi - wvv;
        }
        __syncthreads();
        s_pstart[tid] = incl2 - v2 + s_wsum[warp];
        if (tid == THREADS - 1) s_pstart[NBIN] = incl2 + s_wsum[warp];
        __syncthreads();
    }

    // ============ Phase C: scatter into norm order ============
    for (int j = gtid; j < nmm; j += gstride) {
        float gx = model[3 * j], gy = model[3 * j + 1], gz = model[3 * j + 2];
        float b = fmaf(gx, gx, fmaf(gy, gy, gz * gz));
        int bn = norm_bin(sqrtf(b));
        int pos = s_mstart[bn] + atomicAdd(&g_mcur[bn], 1);
        float* r = g_msp + (size_t)(pos >> 1) * 8;
        int o = pos & 1;
        r[0 + o] = gx; r[2 + o] = gy; r[4 + o] = gz; r[6 + o] = b;
    }
    if ((nmm & 1) && gtid == 0) {
        float* r = g_msp + (size_t)(nmm >> 1) * 8;
        r[1] = 0.f; r[3] = 0.f; r[5] = 0.f; r[7] = BIGF;
    }
    for (int i = gtid; i < ntot; i += gstride) {
        float4 P = g_pu[i];
        int bn = norm_bin(sqrtf(P.w));
        int pos = s_pstart[bn] + atomicAdd(&g_pcur[bn], 1);
        g_ps[pos] = P;
        g_psw[pos] = g_puw[i];
    }
    grid_bar(&g_bar2, GRID);
    if (blockIdx.x == 0) {                 // reset for next replay (shadowed by D)
        g_mhist[tid] = 0; g_phist[tid] = 0; g_mcur[tid] = 0; g_pcur[tid] = 0;
    }

    // ============ Phase D: 256-pred blocks, slab + residual from global ============
    for (int pb = blockIdx.x; pb < nbp; pb += (int)GRID) {
        float a[KP], wgt[KP], rr[KP];
        uint64_t qx2[KP], qy2[KP], qz2[KP];
        #pragma unroll
        for (int k = 0; k < KP; k++) {
            int i = pb * PRED_CTA + k * 32 + lane;
            float qx = 0.f, qy = 0.f, qz = 0.f;
            a[k] = 0.f; wgt[k] = 0.f; rr[k] = 0.f;
            if (i < ntot) {
                float4 P = g_ps[i];
                qx = -2.0f * P.x; qy = -2.0f * P.y; qz = -2.0f * P.z;
                a[k] = P.w; wgt[k] = g_psw[i]; rr[k] = sqrtf(P.w);
            }
            asm("mov.b64 %0, {%1,%1};" : "=l"(qx2[k]) : "f"(qx));
            asm("mov.b64 %0, {%1,%1};" : "=l"(qy2[k]) : "f"(qy));
            asm("mov.b64 %0, {%1,%1};" : "=l"(qz2[k]) : "f"(qz));
        }
        if (tid == 0) {
            s_wlo_i = 0x7f7fffff;
            s_whi_i = 0;
            int imid = pb * PRED_CTA + PRED_CTA / 2;
            if (imid >= ntot) imid = ntot - 1;
            float rmid = sqrtf(g_ps[imid].w);
            int sp = npair < SLABPAIRS ? npair : SLABPAIRS;
            int s0 = (s_mstart[norm_bin(rmid)] >> 1) - sp / 2;
            if (s0 < 0) s0 = 0;
            if (s0 > npair - sp) s0 = npair - sp;
            s_slab0 = s0; s_sp = sp;
        }
        __syncthreads();

        // ---- stage 1: slab scan from global (L2-hot) ----
        float m_lo[KP], m_hi[KP];
        #pragma unroll
        for (int k = 0; k < KP; k++) { m_lo[k] = BIGF; m_hi[k] = BIGF; }
        {
            int sp = s_sp;
            int per = (sp + NWARP - 1) / NWARP;
            int wb = s_slab0 + warp * per;
            int we = wb + per;
            int wend = s_slab0 + sp;
            if (we > wend) we = wend;
            const char* gp = (const char*)g_msp + (size_t)wb * 32;
            #pragma unroll 2
            for (int p = wb; p < we; ++p, gp += 32) {
                uint64_t x2, y2, z2, w2;
                LDG_PAIR(x2, y2, z2, w2, gp)
                PAIRM(x2, y2, z2, w2)
            }
        }
        #pragma unroll
        for (int k = 0; k < KP; k++)
            s_min[warp * PRED_CTA + k * 32 + lane] = fminf(m_lo[k], m_hi[k]);
        __syncthreads();

        // ---- reduce, per-pred window, union (warp 0) ----
        if (warp == 0) {
            #pragma unroll
            for (int k = 0; k < KP; k++) {
                int pidx = k * 32 + lane;
                float m = s_min[pidx];
                #pragma unroll
                for (int s = 1; s < NWARP; s++)
                    m = fminf(m, s_min[s * PRED_CTA + pidx]);
                s_m1[pidx] = m;
                int i = pb * PRED_CTA + pidx;
                if (i < ntot) {
                    float W = sqrtf(fmaxf(a[k] + m, 0.f)) * 1.002f + 1e-5f;
                    float wlo = fmaxf(rr[k] - W, 0.f);
                    float whi = rr[k] + W;
                    atomicMin(&s_wlo_i, __float_as_int(wlo));
                    atomicMax(&s_whi_i, __float_as_int(whi));
                }
            }
        }
        __syncthreads();
        if (tid == 0) {
            float wlo = __int_as_float(s_wlo_i);
            float whi = __int_as_float(s_whi_i);
            int r0p = s_mstart[norm_bin(wlo)] >> 1;
            int r1p = (s_mstart[norm_bin(whi) + 1] + 1) >> 1;
            if (r1p > npair) r1p = npair;
            s_n1 = max(0, s_slab0 - r0p);
            s_n2 = max(0, r1p - (s_slab0 + s_sp));
        }
        __syncthreads();

        // ---- stage 2: residual ranges only (seeded) ----
        int nres = s_n1 + s_n2;
        if (nres > 0) {
            int n1 = s_n1;
            int lo0 = s_slab0 - n1;
            int hi0 = s_slab0 + s_sp;
            #pragma unroll
            for (int k = 0; k < KP; k++) {
                m_lo[k] = s_m1[k * 32 + lane];
                m_hi[k] = BIGF;
            }
            int per = (nres + NWARP - 1) / NWARP;
            int wb = warp * per; if (wb > nres) wb = nres;
            int we = wb + per;   if (we > nres) we = nres;
            #pragma unroll 2
            for (int i = wb; i < we; ++i) {
                int pidx = (i < n1) ? (lo0 + i) : (hi0 + (i - n1));
                const char* gp = (const char*)g_msp + (size_t)pidx * 32;
                uint64_t x2, y2, z2, w2;
                LDG_PAIR(x2, y2, z2, w2, gp)
                PAIRM(x2, y2, z2, w2)
            }
            #pragma unroll
            for (int k = 0; k < KP; k++)
                s_min[warp * PRED_CTA + k * 32 + lane] = fminf(m_lo[k], m_hi[k]);
            __syncthreads();
            if (warp == 0) {
                #pragma unroll
                for (int k = 0; k < KP; k++) {
                    int pidx = k * 32 + lane;
                    float m = s_min[pidx];
                    #pragma unroll
                    for (int s = 1; s < NWARP; s++)
                        m = fminf(m, s_min[s * PRED_CTA + pidx]);
                    s_m1[pidx] = m;
                }
            }
            __syncthreads();
        }

        // ---- block-weighted sum ----
        if (warp == 0) {
            float vsum = 0.0f;
            #pragma unroll
            for (int k = 0; k < KP; k++) {
                int pidx = k * 32 + lane;
                if (pb * PRED_CTA + pidx < ntot)
                    vsum += (a[k] + s_m1[pidx]) * wgt[k];
            }
            #pragma unroll
            for (int o = 16; o > 0; o >>= 1)
                vsum += __shfl_down_sync(0xffffffffu, vsum, o);
            if (lane == 0 && pb < NB_MAX) g_partials[pb] = vsum;
        }
        __syncthreads();
    }

    // ============ final fixed-order reduction ============
    if (tid == 0) {
        __threadfence();
        unsigned int t = atomicAdd(&g_ticket, 1u);
        s_last = (t == GRID - 1u) ? 1 : 0;
    }
    __syncthreads();
    if (s_last && warp == 0) {
        float s = 0.0f;
        for (int b = lane; b < nbp; b += 32)
            s += *((volatile float*)&g_partials[b]);
        #pragma unroll
        for (int o = 16; o > 0; o >>= 1)
            s += __shfl_down_sync(0xffffffffu, s, o);
        if (lane == 0) {
            out[0] = s;
            g_ticket = 0; g_bar1 = 0; g_bar2 = 0;   // reset for replay
        }
    }
}

extern "C" void kernel_launch(void* const* d_in, const int* in_sizes, int n_in,
                              void* d_out, int out_size) {
    const float* vis   = (const float*)d_in[0];  // visual_points  (16384,3)
    const float* tac   = (const float*)d_in[1];  // tactile_points (2048,3)
    const float* model = (const float*)d_in[2];  // model_points   (8192,3)
    const float* scale = (const float*)d_in[3];  // scalar
    const float* state = (const float*)d_in[4];  // (6,)
    float* out = (float*)d_out;

    int nv = in_sizes[0] / 3;
    int nt = in_sizes[1] / 3;
    int nm = in_sizes[2] / 3;

    int ntot = nv + nt;
    int nbp = (ntot + PRED_CTA - 1) / PRED_CTA;   // 72 for default shapes
    if (nbp > NB_MAX) nbp = NB_MAX;
    int grid = 144;                               // all-resident for barriers
    if (grid > 144) grid = 144;

    float wv = 1.0f / (float)nv;
    float wt = 0.1f / (float)nt;

    cd_kernel<<<grid, THREADS>>>(vis, tac, model, scale, state, out,
                                 nv, nt, nm, wv, wt, nbp);
}

// round 17
// speedup vs baseline: 1.3924x; 1.3924x over previous
#include <cuda_runtime.h>
#include <math.h>
#include <cstdint>
#include <float.h>

#define NBIN      512
#define BINSCALE  64.0f
#define THREADS   512
#define NWARP     16
#define NB_MAX    256
#define MAXM      16384
#define MAXP      32768
#define SLABPAIRS 640
#define BUFPAIRS  640          // smem staging buffer (pairs, 32B each)
#define BIGF      3.0e37f

// -------- device scratch (static; no allocations) --------
__device__ float  g_msp[(MAXM / 2 + 1) * 8];   // norm-sorted model, pair-interleaved
__device__ float4 g_pu[MAXP];                  // transformed preds (px,py,pz,a)
__device__ float  g_puw[MAXP];
__device__ float4 g_ps[MAXP];                  // norm-sorted preds
__device__ float  g_psw[MAXP];
__device__ int g_mhist[NBIN], g_phist[NBIN], g_mcur[NBIN], g_pcur[NBIN];
__device__ float g_partials[NB_MAX];
__device__ unsigned int g_bar1, g_bar2, g_ticket;

__device__ __forceinline__ int norm_bin(float r) {
    int b = (int)(r * BINSCALE);
    if (b < 0) b = 0;
    if (b > NBIN - 1) b = NBIN - 1;
    return b;
}

__device__ __forceinline__ void grid_bar(unsigned int* ctr, unsigned int tgt) {
    __syncthreads();
    if (threadIdx.x == 0) {
        __threadfence();
        atomicAdd(ctr, 1u);
        while (*((volatile unsigned int*)ctr) < tgt) { }
        __threadfence();
    }
    __syncthreads();
}

// packed f32x2 distance + min for one pair record against 4 preds
#define PAIRM(X2, Y2, Z2, W2)                                                  \
    {                                                                          \
        _Pragma("unroll")                                                      \
        for (int k = 0; k < 4; k++) {                                          \
            uint64_t d2;                                                       \
            asm("fma.rn.f32x2 %0, %1, %2, %3;" : "=l"(d2)                      \
                : "l"(qz2[k]), "l"(Z2), "l"(W2));                              \
            asm("fma.rn.f32x2 %0, %1, %2, %0;" : "+l"(d2)                      \
                : "l"(qy2[k]), "l"(Y2));                                       \
            asm("fma.rn.f32x2 %0, %1, %2, %0;" : "+l"(d2)                      \
                : "l"(qx2[k]), "l"(X2));                                       \
            float dlo, dhi;                                                    \
            asm("mov.b64 {%0,%1}, %2;" : "=f"(dlo), "=f"(dhi) : "l"(d2));      \
            m_lo[k] = fminf(m_lo[k], dlo);                                     \
            m_hi[k] = fminf(m_hi[k], dhi);                                     \
        }                                                                      \
    }

#define LDG_PAIR(X2, Y2, Z2, W2, GP)                                           \
    asm("ld.global.nc.v2.u64 {%0,%1}, [%2];"                                   \
        : "=l"(X2), "=l"(Y2) : "l"(GP));                                       \
    asm("ld.global.nc.v2.u64 {%0,%1}, [%2+16];"                                \
        : "=l"(Z2), "=l"(W2) : "l"(GP));

#define LDS_PAIR(X2, Y2, Z2, W2, AP)                                           \
    asm("ld.shared.v2.u64 {%0,%1}, [%2];"                                      \
        : "=l"(X2), "=l"(Y2) : "r"(AP));                                       \
    asm("ld.shared.v2.u64 {%0,%1}, [%2+16];"                                   \
        : "=l"(Z2), "=l"(W2) : "r"(AP));

__global__ __launch_bounds__(THREADS, 1)
void cd_kernel(const float* __restrict__ vis,
               const float* __restrict__ tac,
               const float* __restrict__ model,
               const float* __restrict__ scale,
               const float* __restrict__ state,
               float* __restrict__ out,
               int nv, int nt, int nm,
               float wv, float wt, int nbp) {
    extern __shared__ float s_buf[];            // BUFPAIRS pair records
    __shared__ float s_par[13];
    __shared__ float s_min[NWARP * 128];
    __shared__ float s_m1[128];
    __shared__ int s_mstart[NBIN + 1];
    __shared__ int s_pstart[NBIN + 1];
    __shared__ int s_wsum[NWARP];
    __shared__ int s_wlo_i, s_whi_i, s_slab0, s_sp, s_n1, s_n2, s_last;

    const int tid  = threadIdx.x;
    const int lane = tid & 31;
    const int warp = tid >> 5;
    const int ntot0 = nv + nt;
    const int ntot = ntot0 < MAXP ? ntot0 : MAXP;
    const int nmm  = nm < MAXM ? nm : MAXM;
    const int npair = (nmm + 1) >> 1;
    const unsigned int GRID = gridDim.x;
    const int gstride = (int)GRID * THREADS;
    const int gtid = blockIdx.x * THREADS + tid;

    uint32_t bufb;
    {
        uint64_t t64;
        asm("cvta.to.shared.u64 %0, %1;" : "=l"(t64) : "l"(s_buf));
        bufb = (uint32_t)t64;
    }

    // ---- transform params ----
    if (tid == 0) {
        float oxs = state[3], oys = state[4], ozs = state[5];
        float sx = sinf(oxs), cx = cosf(oxs);
        float sy = sinf(oys), cy = cosf(oys);
        float sz = sinf(ozs), cz = cosf(ozs);
        s_par[0] = cz * cy;
        s_par[1] = cz * sy * sx - sz * cx;
        s_par[2] = cz * sy * cx + sz * sx;
        s_par[3] = sz * cy;
        s_par[4] = sz * sy * sx + cz * cx;
        s_par[5] = sz * sy * cx - cz * sx;
        s_par[6] = -sy;
        s_par[7] = cy * sx;
        s_par[8] = cy * cx;
        s_par[9]  = state[0];
        s_par[10] = state[1];
        s_par[11] = state[2];
        s_par[12] = 1.0f / scale[0];
    }
    __syncthreads();

    // ============ Phase A: histograms + pred transform ============
    for (int j = gtid; j < nmm; j += gstride) {
        float gx = model[3 * j], gy = model[3 * j + 1], gz = model[3 * j + 2];
        float b = fmaf(gx, gx, fmaf(gy, gy, gz * gz));
        atomicAdd(&g_mhist[norm_bin(sqrtf(b))], 1);
    }
    for (int i = gtid; i < ntot; i += gstride) {
        const float* src; int idx; float w;
        if (i < nv) { src = vis; idx = i;      w = wv; }
        else        { src = tac; idx = i - nv; w = wt; }
        float vx = src[3 * idx + 0] - s_par[9];
        float vy = src[3 * idx + 1] - s_par[10];
        float vz = src[3 * idx + 2] - s_par[11];
        float inv_s = s_par[12];
        float px = (vx * s_par[0] + vy * s_par[3] + vz * s_par[6]) * inv_s;
        float py = (vx * s_par[1] + vy * s_par[4] + vz * s_par[7]) * inv_s;
        float pz = (vx * s_par[2] + vy * s_par[5] + vz * s_par[8]) * inv_s;
        float a = fmaf(px, px, fmaf(py, py, pz * pz));
        g_pu[i]  = make_float4(px, py, pz, a);
        g_puw[i] = w;
        atomicAdd(&g_phist[norm_bin(sqrtf(a))], 1);
    }
    grid_bar(&g_bar1, GRID);

    // ============ Phase B: warp-shfl prefix scans (every CTA) ============
    {
        int v = g_mhist[tid];
        int incl = v;
        #pragma unroll
        for (int o = 1; o < 32; o <<= 1) {
            int t = __shfl_up_sync(0xffffffffu, incl, o);
            if (lane >= o) incl += t;
        }
        if (lane == 31) s_wsum[warp] = incl;
        __syncthreads();
        if (warp == 0) {
            int wvv = (lane < NWARP) ? s_wsum[lane] : 0;
            int wi = wvv;
            #pragma unroll
            for (int o = 1; o < 16; o <<= 1) {
                int t = __shfl_up_sync(0xffffffffu, wi, o);
                if (lane >= o) wi += t;
            }
            if (lane < NWARP) s_wsum[lane] = wi - wvv;
        }
        __syncthreads();
        s_mstart[tid] = incl - v + s_wsum[warp];
        if (tid == THREADS - 1) s_mstart[NBIN] = incl + s_wsum[warp];
        __syncthreads();

        int v2 = g_phist[tid];
        int incl2 = v2;
        #pragma unroll
        for (int o = 1; o < 32; o <<= 1) {
            int t = __shfl_up_sync(0xffffffffu, incl2, o);
            if (lane >= o) incl2 += t;
        }
        if (lane == 31) s_wsum[warp] = incl2;
        __syncthreads();
        if (warp == 0) {
            int wvv = (lane < NWARP) ? s_wsum[lane] : 0;
            int wi = wvv;
            #pragma unroll
            for (int o = 1; o < 16; o <<= 1) {
                int t = __shfl_up_sync(0xffffffffu, wi, o);
                if (lane >= o) wi += t;
            }
            if (lane < NWARP) s_wsum[lane] = wi - wvv;
        }
        __syncthreads();
        s_pstart[tid] = incl2 - v2 + s_wsum[warp];
        if (tid == THREADS - 1) s_pstart[NBIN] = incl2 + s_wsum[warp];
        __syncthreads();
    }

    // ============ Phase C: scatter into norm order ============
    for (int j = gtid; j < nmm; j += gstride) {
        float gx = model[3 * j], gy = model[3 * j + 1], gz = model[3 * j + 2];
        float b = fmaf(gx, gx, fmaf(gy, gy, gz * gz));
        int bn = norm_bin(sqrtf(b));
        int pos = s_mstart[bn] + atomicAdd(&g_mcur[bn], 1);
        float* r = g_msp + (size_t)(pos >> 1) * 8;
        int o = pos & 1;
        r[0 + o] = gx; r[2 + o] = gy; r[4 + o] = gz; r[6 + o] = b;
    }
    if ((nmm & 1) && gtid == 0) {
        float* r = g_msp + (size_t)(nmm >> 1) * 8;
        r[1] = 0.f; r[3] = 0.f; r[5] = 0.f; r[7] = BIGF;
    }
    for (int i = gtid; i < ntot; i += gstride) {
        float4 P = g_pu[i];
        int bn = norm_bin(sqrtf(P.w));
        int pos = s_pstart[bn] + atomicAdd(&g_pcur[bn], 1);
        g_ps[pos] = P;
        g_psw[pos] = g_puw[i];
    }
    grid_bar(&g_bar2, GRID);
    if (blockIdx.x == 0) {                 // reset for next replay (shadowed by D)
        g_mhist[tid] = 0; g_phist[tid] = 0; g_mcur[tid] = 0; g_pcur[tid] = 0;
    }

    // ============ Phase D: slab (smem-staged) + residual ============
    for (int pb = blockIdx.x; pb < nbp; pb += (int)GRID) {
        float a[4], wgt[4], rr[4];
        uint64_t qx2[4], qy2[4], qz2[4];
        #pragma unroll
        for (int k = 0; k < 4; k++) {
            int i = pb * 128 + k * 32 + lane;
            float qx = 0.f, qy = 0.f, qz = 0.f;
            a[k] = 0.f; wgt[k] = 0.f; rr[k] = 0.f;
            if (i < ntot) {
                float4 P = g_ps[i];
                qx = -2.0f * P.x; qy = -2.0f * P.y; qz = -2.0f * P.z;
                a[k] = P.w; wgt[k] = g_psw[i]; rr[k] = sqrtf(P.w);
            }
            asm("mov.b64 %0, {%1,%1};" : "=l"(qx2[k]) : "f"(qx));
            asm("mov.b64 %0, {%1,%1};" : "=l"(qy2[k]) : "f"(qy));
            asm("mov.b64 %0, {%1,%1};" : "=l"(qz2[k]) : "f"(qz));
        }
        if (tid == 0) {
            s_wlo_i = 0x7f7fffff;
            s_whi_i = 0;
            int imid = pb * 128 + 64; if (imid >= ntot) imid = ntot - 1;
            float rmid = sqrtf(g_ps[imid].w);
            int sp = npair < SLABPAIRS ? npair : SLABPAIRS;
            int s0 = (s_mstart[norm_bin(rmid)] >> 1) - sp / 2;
            if (s0 < 0) s0 = 0;
            if (s0 > npair - sp) s0 = npair - sp;
            s_slab0 = s0; s_sp = sp;
        }
        __syncthreads();

        // ---- stage 1: coalesced copy slab into smem, then LDS scan ----
        {
            int sp = s_sp;
            const uint4* src = (const uint4*)(g_msp + (size_t)s_slab0 * 8);
            uint4* dst = (uint4*)s_buf;
            for (int t = tid; t < sp * 2; t += THREADS) dst[t] = src[t];
        }
        __syncthreads();

        float m_lo[4], m_hi[4];
        #pragma unroll
        for (int k = 0; k < 4; k++) { m_lo[k] = BIGF; m_hi[k] = BIGF; }
        {
            int sp = s_sp;
            int per = (sp + NWARP - 1) / NWARP;
            int wb = warp * per; if (wb > sp) wb = sp;
            int we = wb + per;   if (we > sp) we = sp;
            uint32_t ap = bufb + (uint32_t)wb * 32u;
            #pragma unroll 4
            for (int p = wb; p < we; ++p, ap += 32u) {
                uint64_t x2, y2, z2, w2;
                LDS_PAIR(x2, y2, z2, w2, ap)
                PAIRM(x2, y2, z2, w2)
            }
        }
        #pragma unroll
        for (int k = 0; k < 4; k++)
            s_min[warp * 128 + k * 32 + lane] = fminf(m_lo[k], m_hi[k]);
        __syncthreads();

        // ---- reduce, per-pred window, union (warp 0) ----
        if (warp == 0) {
            #pragma unroll
            for (int k = 0; k < 4; k++) {
                int pidx = k * 32 + lane;
                float m = s_min[pidx];
                #pragma unroll
                for (int s = 1; s < NWARP; s++) m = fminf(m, s_min[s * 128 + pidx]);
                s_m1[pidx] = m;
                int i = pb * 128 + pidx;
                if (i < ntot) {
                    float W = sqrtf(fmaxf(a[k] + m, 0.f)) * 1.002f + 1e-5f;
                    float wlo = fmaxf(rr[k] - W, 0.f);
                    float whi = rr[k] + W;
                    atomicMin(&s_wlo_i, __float_as_int(wlo));
                    atomicMax(&s_whi_i, __float_as_int(whi));
                }
            }
        }
        __syncthreads();
        if (tid == 0) {
            float wlo = __int_as_float(s_wlo_i);
            float whi = __int_as_float(s_whi_i);
            int r0p = s_mstart[norm_bin(wlo)] >> 1;
            int r1p = (s_mstart[norm_bin(whi) + 1] + 1) >> 1;
            if (r1p > npair) r1p = npair;
            s_n1 = max(0, s_slab0 - r0p);
            s_n2 = max(0, r1p - (s_slab0 + s_sp));
        }
        __syncthreads();

        // ---- stage 2: residual ranges (smem-staged when small) ----
        int nres = s_n1 + s_n2;
        if (nres > 0) {
            int n1 = s_n1;
            int lo0 = s_slab0 - n1;
            int hi0 = s_slab0 + s_sp;
            #pragma unroll
            for (int k = 0; k < 4; k++) { m_lo[k] = s_m1[k * 32 + lane]; m_hi[k] = BIGF; }

            if (nres <= BUFPAIRS) {
                // coalesced copy both ranges contiguously into s_buf
                uint4* dst = (uint4*)s_buf;
                for (int t = tid; t < nres * 2; t += THREADS) {
                    int pr = t >> 1, hf = t & 1;
                    int pidx = (pr < n1) ? (lo0 + pr) : (hi0 + (pr - n1));
                    dst[t] = ((const uint4*)(g_msp + (size_t)pidx * 8))[hf];
                }
                __syncthreads();
                int per = (nres + NWARP - 1) / NWARP;
                int wb = warp * per; if (wb > nres) wb = nres;
                int we = wb + per;   if (we > nres) we = nres;
                uint32_t ap = bufb + (uint32_t)wb * 32u;
                #pragma unroll 4
                for (int p = wb; p < we; ++p, ap += 32u) {
                    uint64_t x2, y2, z2, w2;
                    LDS_PAIR(x2, y2, z2, w2, ap)
                    PAIRM(x2, y2, z2, w2)
                }
            } else {
                int per = (nres + NWARP - 1) / NWARP;
                int wb = warp * per; if (wb > nres) wb = nres;
                int we = wb + per;   if (we > nres) we = nres;
                #pragma unroll 4
                for (int i = wb; i < we; ++i) {
                    int pidx = (i < n1) ? (lo0 + i) : (hi0 + (i - n1));
                    const char* gp = (const char*)g_msp + (size_t)pidx * 32;
                    uint64_t x2, y2, z2, w2;
                    LDG_PAIR(x2, y2, z2, w2, gp)
                    PAIRM(x2, y2, z2, w2)
                }
            }
            #pragma unroll
            for (int k = 0; k < 4; k++)
                s_min[warp * 128 + k * 32 + lane] = fminf(m_lo[k], m_hi[k]);
            __syncthreads();
            if (warp == 0) {
                #pragma unroll
                for (int k = 0; k < 4; k++) {
                    int pidx = k * 32 + lane;
                    float m = s_min[pidx];
                    #pragma unroll
                    for (int s = 1; s < NWARP; s++) m = fminf(m, s_min[s * 128 + pidx]);
                    s_m1[pidx] = m;
                }
            }
            __syncthreads();
        }

        // ---- block-weighted sum ----
        if (warp == 0) {
            float vsum = 0.0f;
            #pragma unroll
            for (int k = 0; k < 4; k++) {
                int pidx = k * 32 + lane;
                if (pb * 128 + pidx < ntot) vsum += (a[k] + s_m1[pidx]) * wgt[k];
            }
            #pragma unroll
            for (int o = 16; o > 0; o >>= 1)
                vsum += __shfl_down_sync(0xffffffffu, vsum, o);
            if (lane == 0 && pb < NB_MAX) g_partials[pb] = vsum;
        }
        __syncthreads();
    }

    // ============ final fixed-order reduction ============
    if (tid == 0) {
        __threadfence();
        unsigned int t = atomicAdd(&g_ticket, 1u);
        s_last = (t == GRID - 1u) ? 1 : 0;
    }
    __syncthreads();
    if (s_last && warp == 0) {
        float s = 0.0f;
        for (int b = lane; b < nbp; b += 32)
            s += *((volatile float*)&g_partials[b]);
        #pragma unroll
        for (int o = 16; o > 0; o >>= 1)
            s += __shfl_down_sync(0xffffffffu, s, o);
        if (lane == 0) {
            out[0] = s;
            g_ticket = 0; g_bar1 = 0; g_bar2 = 0;   // reset for replay
        }
    }
}

extern "C" void kernel_launch(void* const* d_in, const int* in_sizes, int n_in,
                              void* d_out, int out_size) {
    const float* vis   = (const float*)d_in[0];  // visual_points  (16384,3)
    const float* tac   = (const float*)d_in[1];  // tactile_points (2048,3)
    const float* model = (const float*)d_in[2];  // model_points   (8192,3)
    const float* scale = (const float*)d_in[3];  // scalar
    const float* state = (const float*)d_in[4];  // (6,)
    float* out = (float*)d_out;

    int nv = in_sizes[0] / 3;
    int nt = in_sizes[1] / 3;
    int nm = in_sizes[2] / 3;

    int ntot = nv + nt;
    int nbp = (ntot + 127) / 128;               // 144 for default shapes
    if (nbp > NB_MAX) nbp = NB_MAX;
    int grid = nbp < 144 ? nbp : 144;           // all-resident for barriers

    float wv = 1.0f / (float)nv;
    float wt = 0.1f / (float)nt;

    size_t smem = (size_t)BUFPAIRS * 32;        // 20480 B
    cd_kernel<<<grid, THREADS, smem>>>(vis, tac, model, scale, state, out,
                                       nv, nt, nm, wv, wt, nbp);
}